// round 5
// baseline (speedup 1.0000x reference)
#include <cuda_runtime.h>
#include <cstdint>

#define NN 100000
#define NE 1600000
#define NF 128
#define HD 64

// ---------------- scratch (no allocs allowed) ----------------
__device__ __align__(16) float g_dinv[NN];
__device__ __align__(16) float g_t  [NN * HD];   // h @ W (layer1: unscaled; 2/3: *dinv[row])
__device__ __align__(16) float g_h  [NN * HD];   // layer output
__device__ int g_deg[NN];
__device__ int g_cursor[NN];
__device__ int g_rowstart[NN + 1];
__device__ int g_csr[NE];
__device__ float g_loss;
__device__ int   g_lsum;

// ---------------- 1: init (zero deg, loss; label sum) ----------------
__global__ void k_init(const int* __restrict__ labels) {
    int i = blockIdx.x * blockDim.x + threadIdx.x;
    if (i == 0) { g_loss = 0.f; g_lsum = 0; }
    int v = 0;
    if (i < NN) { g_deg[i] = 0; v = labels[i]; }
    #pragma unroll
    for (int off = 16; off; off >>= 1) v += __shfl_down_sync(0xffffffffu, v, off);
    if ((threadIdx.x & 31) == 0 && v) atomicAdd(&g_lsum, v);
}

// ---------------- 2: histogram destinations ----------------
__global__ void k_count(const int* __restrict__ ei) {
    int e = blockIdx.x * blockDim.x + threadIdx.x;
    if (e < NE) {
        unsigned c = (unsigned)ei[NE + e];
        if (c < NN) atomicAdd(&g_deg[c], 1);
    }
}

// ---------------- 3: 1-block scan -> rowstart, cursor, dinv ----------------
__global__ void k_scan() {
    const int T = 1024;
    const int CH = (NN + T - 1) / T;   // 98
    __shared__ int sh[T];
    int tid = threadIdx.x;
    int lo = tid * CH, hi = lo + CH; if (hi > NN) hi = NN;
    int s = 0;
    for (int i = lo; i < hi; i++) s += g_deg[i];
    sh[tid] = s;
    __syncthreads();
    for (int off = 1; off < T; off <<= 1) {
        int v = (tid >= off) ? sh[tid - off] : 0;
        __syncthreads();
        sh[tid] += v;
        __syncthreads();
    }
    int run = sh[tid] - s;   // exclusive
    for (int i = lo; i < hi; i++) {
        int d = g_deg[i];
        g_rowstart[i] = run;
        g_cursor[i]   = run;
        g_dinv[i]     = rsqrtf((float)(d + 1));  // +1 self loop
        run += d;
    }
    if (tid == T - 1) g_rowstart[NN] = run;
}

// ---------------- GEMM: t[i,:] = (hin[i,:] @ W) (* dinv[i] if PRESCALE) ------
// block 256 = 64 cols x 4 row-threads; 32-row tile; 8 rows/thread register acc.
template <int K, bool USEG, bool PRESCALE>
__global__ void k_gemm(const float* __restrict__ hin, const float* __restrict__ W) {
    __shared__ __align__(16) float sW[K * HD];           // K=128: 32KB, K=64: 16KB
    __shared__ __align__(16) float4 srow[32][K / 4];     // K=128: 16KB, K=64: 8KB
    const float* src = USEG ? g_h : hin;
    int tid = threadIdx.x;
    for (int j = tid; j < K * HD / 4; j += 256)
        ((float4*)sW)[j] = ((const float4*)W)[j];

    int c  = tid & 63;     // column 0..63
    int rt = tid >> 6;     // row-thread 0..3, owns rows rt*8..rt*8+7

    for (int rb = blockIdx.x * 32; rb < NN; rb += gridDim.x * 32) {
        __syncthreads();
        for (int j = tid; j < 32 * (K / 4); j += 256) {
            int r = j / (K / 4), kk = j % (K / 4);
            srow[r][kk] = ((const float4*)(src + (size_t)(rb + r) * K))[kk];
        }
        __syncthreads();

        float acc[8];
        #pragma unroll
        for (int rr = 0; rr < 8; rr++) acc[rr] = 0.f;

        #pragma unroll
        for (int k4 = 0; k4 < K / 4; k4++) {
            float w0 = sW[(4 * k4 + 0) * HD + c];
            float w1 = sW[(4 * k4 + 1) * HD + c];
            float w2 = sW[(4 * k4 + 2) * HD + c];
            float w3 = sW[(4 * k4 + 3) * HD + c];
            #pragma unroll
            for (int rr = 0; rr < 8; rr++) {
                float4 h = srow[rt * 8 + rr][k4];
                acc[rr] = fmaf(h.x, w0, acc[rr]);
                acc[rr] = fmaf(h.y, w1, acc[rr]);
                acc[rr] = fmaf(h.z, w2, acc[rr]);
                acc[rr] = fmaf(h.w, w3, acc[rr]);
            }
        }
        #pragma unroll
        for (int rr = 0; rr < 8; rr++) {
            int gr = rb + rt * 8 + rr;
            g_t[(size_t)gr * HD + c] = PRESCALE ? acc[rr] * g_dinv[gr] : acc[rr];
        }
    }
}

// ---------------- aggregate core (16 threads per node) ----------------
template <bool SCALE_SRC>
__device__ __forceinline__ float4 agg_node(int node, int part) {
    const float4* __restrict__ t4 = (const float4*)g_t;
    int s = g_rowstart[node];
    int e = g_rowstart[node + 1];

    float4 acc = t4[(size_t)node * 16 + part];   // self loop
    if (SCALE_SRC) {
        float dn = g_dinv[node];
        acc.x *= dn; acc.y *= dn; acc.z *= dn; acc.w *= dn;
    }
    int i = s;
    for (; i + 4 <= e; i += 4) {
        int s0 = g_csr[i], s1 = g_csr[i + 1], s2 = g_csr[i + 2], s3 = g_csr[i + 3];
        float4 v0 = t4[(size_t)s0 * 16 + part];
        float4 v1 = t4[(size_t)s1 * 16 + part];
        float4 v2 = t4[(size_t)s2 * 16 + part];
        float4 v3 = t4[(size_t)s3 * 16 + part];
        if (SCALE_SRC) {
            float d0 = g_dinv[s0], d1 = g_dinv[s1], d2 = g_dinv[s2], d3 = g_dinv[s3];
            acc.x = fmaf(d0, v0.x, acc.x); acc.y = fmaf(d0, v0.y, acc.y);
            acc.z = fmaf(d0, v0.z, acc.z); acc.w = fmaf(d0, v0.w, acc.w);
            acc.x = fmaf(d1, v1.x, acc.x); acc.y = fmaf(d1, v1.y, acc.y);
            acc.z = fmaf(d1, v1.z, acc.z); acc.w = fmaf(d1, v1.w, acc.w);
            acc.x = fmaf(d2, v2.x, acc.x); acc.y = fmaf(d2, v2.y, acc.y);
            acc.z = fmaf(d2, v2.z, acc.z); acc.w = fmaf(d2, v2.w, acc.w);
            acc.x = fmaf(d3, v3.x, acc.x); acc.y = fmaf(d3, v3.y, acc.y);
            acc.z = fmaf(d3, v3.z, acc.z); acc.w = fmaf(d3, v3.w, acc.w);
        } else {
            acc.x += v0.x + v1.x + v2.x + v3.x;
            acc.y += v0.y + v1.y + v2.y + v3.y;
            acc.z += v0.z + v1.z + v2.z + v3.z;
            acc.w += v0.w + v1.w + v2.w + v3.w;
        }
    }
    for (; i < e; i++) {
        int s0 = g_csr[i];
        float4 v = t4[(size_t)s0 * 16 + part];
        if (SCALE_SRC) {
            float d0 = g_dinv[s0];
            acc.x = fmaf(d0, v.x, acc.x); acc.y = fmaf(d0, v.y, acc.y);
            acc.z = fmaf(d0, v.z, acc.z); acc.w = fmaf(d0, v.w, acc.w);
        } else {
            acc.x += v.x; acc.y += v.y; acc.z += v.z; acc.w += v.w;
        }
    }
    return acc;
}

// ---------------- agg + combine -> g_h ----------------
template <bool SCALE_SRC>
__global__ void k_agg(const float* __restrict__ b) {
    int tid  = threadIdx.x;
    int node = blockIdx.x * 16 + (tid >> 4);
    int part = tid & 15;

    float4 acc = agg_node<SCALE_SRC>(node, part);
    float d = g_dinv[node];
    float4 bb = *(const float4*)&b[part * 4];
    float4 o;
    o.x = fmaxf(fmaf(d, acc.x, bb.x), 0.f);
    o.y = fmaxf(fmaf(d, acc.y, bb.y), 0.f);
    o.z = fmaxf(fmaf(d, acc.z, bb.z), 0.f);
    o.w = fmaxf(fmaf(d, acc.w, bb.w), 0.f);
    ((float4*)g_h)[(size_t)node * 16 + part] = o;
}

// ---------------- agg3 fused with MLP head + loss ----------------
__global__ void k_agg_head(const float* __restrict__ b,
                           const float* __restrict__ lW1, const float* __restrict__ lb1,
                           const float* __restrict__ lW2, const float* __restrict__ lb2,
                           const int* __restrict__ labels, float* __restrict__ out_p) {
    __shared__ float sW1[HD * 8];
    __shared__ float sb1[8];
    __shared__ float sW2[8];
    __shared__ float sb2;
    __shared__ float swsum[8];
    int tid = threadIdx.x;
    for (int j = tid; j < HD * 8; j += 256) sW1[j] = lW1[j];
    if (tid < 8) { sb1[tid] = lb1[tid]; sW2[tid] = lW2[tid]; }
    if (tid == 0) sb2 = lb2[0];
    __syncthreads();

    int node = blockIdx.x * 16 + (tid >> 4);   // NN % 16 == 0 -> always valid
    int part = tid & 15;

    float4 acc = agg_node<false>(node, part);
    float d = g_dinv[node];
    float4 bb = *(const float4*)&b[part * 4];
    float4 h;
    h.x = fmaxf(fmaf(d, acc.x, bb.x), 0.f);
    h.y = fmaxf(fmaf(d, acc.y, bb.y), 0.f);
    h.z = fmaxf(fmaf(d, acc.z, bb.z), 0.f);
    h.w = fmaxf(fmaf(d, acc.w, bb.w), 0.f);

    // partial z[8]: this thread covers k = part*4 .. part*4+3
    float z[8];
    #pragma unroll
    for (int o = 0; o < 8; o++) {
        int k0 = part * 4;
        float zz;
        zz  = h.x * sW1[(k0 + 0) * 8 + o];
        zz  = fmaf(h.y, sW1[(k0 + 1) * 8 + o], zz);
        zz  = fmaf(h.z, sW1[(k0 + 2) * 8 + o], zz);
        zz  = fmaf(h.w, sW1[(k0 + 3) * 8 + o], zz);
        z[o] = zz;
    }
    // reduce across the 16 threads of this node
    #pragma unroll
    for (int off = 8; off; off >>= 1) {
        #pragma unroll
        for (int o = 0; o < 8; o++)
            z[o] += __shfl_down_sync(0xffffffffu, z[o], off, 16);
    }

    float term = 0.f;
    if (part == 0) {
        float z2 = sb2;
        #pragma unroll
        for (int o = 0; o < 8; o++) z2 = fmaf(fmaxf(z[o] + sb1[o], 0.f), sW2[o], z2);
        float p = 1.f / (1.f + expf(-z2));
        out_p[node] = p;

        float pm = (float)g_lsum * (1.0f / NN);
        float y = (float)labels[node];
        float w = y * (1.f - pm) + (1.f - y) * pm;
        float pc = fminf(fmaxf(p, 1e-7f), 1.f - 1e-7f);
        float bce = -(y * logf(pc) + (1.f - y) * logf(1.f - pc));
        term = w * bce;
    }
    // warp reduce (terms live on lanes 0 and 16)
    #pragma unroll
    for (int off = 16; off; off >>= 1) term += __shfl_down_sync(0xffffffffu, term, off);
    if ((tid & 31) == 0) swsum[tid >> 5] = term;
    __syncthreads();
    if (tid == 0) {
        float s = 0.f;
        #pragma unroll
        for (int k2 = 0; k2 < 8; k2++) s += swsum[k2];
        atomicAdd(&g_loss, s);
    }
}

// ---------------- fill CSR ----------------
__global__ void k_fill(const int* __restrict__ ei) {
    int e = blockIdx.x * blockDim.x + threadIdx.x;
    if (e >= NE) return;
    unsigned src = (unsigned)ei[e];
    unsigned dst = (unsigned)ei[NE + e];
    if (src >= NN || dst >= NN) return;
    int pos = atomicAdd(&g_cursor[dst], 1);
    g_csr[pos] = (int)src;
}

__global__ void k_final(float* __restrict__ out) {
    out[0] = g_loss * (1.0f / NN);
}

// ---------------- launch ----------------
extern "C" void kernel_launch(void* const* d_in, const int* in_sizes, int n_in,
                              void* d_out, int out_size) {
    const float* x      = (const float*)d_in[0];
    const int*   ei     = (const int*)d_in[1];
    const int*   labels = (const int*)d_in[2];
    const float* W1  = (const float*)d_in[3];
    const float* b1  = (const float*)d_in[4];
    const float* W2  = (const float*)d_in[5];
    const float* b2  = (const float*)d_in[6];
    const float* W3  = (const float*)d_in[7];
    const float* b3  = (const float*)d_in[8];
    const float* lW1 = (const float*)d_in[9];
    const float* lb1 = (const float*)d_in[10];
    const float* lW2 = (const float*)d_in[11];
    const float* lb2 = (const float*)d_in[12];

    float* out = (float*)d_out;
    int loss_elems = out_size - NN;
    float* out_p = out + (loss_elems > 0 ? loss_elems : 0);

    const int TPB = 256;
    const int NB_N = (NN + TPB - 1) / TPB;
    const int NB_E = (NE + TPB - 1) / TPB;
    const int agg_blocks = NN / 16;   // 6250

    k_init <<<NB_N, TPB>>>(labels);                       // 1
    k_count<<<NB_E, TPB>>>(ei);                           // 2
    k_scan <<<1, 1024>>>();                               // 3
    k_gemm<NF, false, false><<<592, TPB>>>(x, W1);        // 4  <- profiled
    k_fill <<<NB_E, TPB>>>(ei);                           // 5
    k_agg<true><<<agg_blocks, TPB>>>(b1);                 // 6

    k_gemm<HD, true, true><<<592, TPB>>>(nullptr, W2);    // 7
    k_agg<false><<<agg_blocks, TPB>>>(b2);                // 8

    k_gemm<HD, true, true><<<592, TPB>>>(nullptr, W3);    // 9
    k_agg_head<<<agg_blocks, TPB>>>(b3, lW1, lb1, lW2, lb2, labels, out_p);  // 10
    if (loss_elems > 0) k_final<<<1, 1>>>(out);           // 11
}